// round 16
// baseline (speedup 1.0000x reference)
#include <cuda_runtime.h>
#include <cuda_fp16.h>
#include <cstdint>

// ---------------------------------------------------------------- problem
#define BATCH 4
#define SEQ   2048
#define DIM   1024
#define MTOT  (BATCH * SEQ)          // 8192

// ---------------------------------------------------------------- GEMM tile
#define TM   128
#define TN   256
#define BKH  32                      // K halves per stage (2 x k16)
#define SREG 40                      // smem row stride in halves (80 B)
#define ABUF (TM * SREG * 2)         // 10240 B per A stage
#define BBUF (TN * SREG * 2)         // 20480 B per B stage
#define STAGES 4
#define SMEM_TOTAL (STAGES * (ABUF + BBUF))   // 122880 B

// ---------------------------------------------------------------- scratch
__device__ __align__(1024) __half g_xh  [(size_t)MTOT * DIM];        // x fp16
__device__ __align__(1024) __half g_wth [3][(size_t)DIM * DIM];      // W^T fp16
__device__ __align__(1024) __half g_qkvh[3][(size_t)MTOT * DIM];     // Q,K,V fp16
__device__ __align__(1024) __half g_vth [(size_t)MTOT * DIM];        // V^T fp16
__device__ __align__(1024) float  g_s   [(size_t)BATCH * SEQ * SEQ]; // scores fp32
__device__ __align__(1024) __half g_ph  [(size_t)BATCH * SEQ * SEQ]; // P fp16

// ---------------------------------------------------------------- helpers
__device__ __forceinline__ uint32_t f2h2(float lo, float hi) {   // packed {lo,hi}
    uint32_t r; asm("cvt.rn.f16x2.f32 %0, %1, %2;" : "=r"(r) : "f"(hi), "f"(lo)); return r;
}
__device__ __forceinline__ uint32_t smem_u32(const void* p) {
    uint32_t a;
    asm("{ .reg .u64 t; cvta.to.shared.u64 t, %1; cvt.u32.u64 %0, t; }" : "=r"(a) : "l"(p));
    return a;
}
__device__ __forceinline__ void mma_f16(float* d, const uint32_t* a, const uint32_t* b) {
    asm volatile(
        "mma.sync.aligned.m16n8k16.row.col.f32.f16.f16.f32 "
        "{%0,%1,%2,%3}, {%4,%5,%6,%7}, {%8,%9}, {%0,%1,%2,%3};"
        : "+f"(d[0]), "+f"(d[1]), "+f"(d[2]), "+f"(d[3])
        : "r"(a[0]), "r"(a[1]), "r"(a[2]), "r"(a[3]), "r"(b[0]), "r"(b[1]));
}
__device__ __forceinline__ void ldmx4(uint32_t* r, uint32_t addr) {
    asm volatile("ldmatrix.sync.aligned.m8n8.x4.shared.b16 {%0,%1,%2,%3}, [%4];"
                 : "=r"(r[0]), "=r"(r[1]), "=r"(r[2]), "=r"(r[3]) : "r"(addr));
}
__device__ __forceinline__ void cp16(uint32_t dst, const void* src) {
    asm volatile("cp.async.cg.shared.global [%0], [%1], 16;" :: "r"(dst), "l"(src));
}
#define CP_COMMIT() asm volatile("cp.async.commit_group;" ::: "memory")
#define CP_WAIT2()  asm volatile("cp.async.wait_group 2;" ::: "memory")

// ---------------------------------------------------------------------------
// fp16 tensor-core GEMM (fp32 accum): C[M,N] = A[M,K] * B[N,K]^T.
// A,B fp16 K-major in gmem. CTA 128x256, warp tile 64x64, 8 warps, BK=32.
// 4-stage cp.async pipeline: wait_group(2) -> barrier -> issue stage it+3
// (into the buffer whose readers just finished) -> mma on stage it.
// All 16 ldmatrix of a stage are hoisted ahead of the 64-mma chain.
// HOUT: write C as fp16 (else fp32). CAUSAL / KLIM as before.
// ---------------------------------------------------------------------------
template <int CAUSAL, int KLIM, int HOUT>
__global__ __launch_bounds__(256, 1)
void mma_gemm(const __half* __restrict__ A, const __half* __restrict__ B,
              void* __restrict__ Cv, int K, int lda, int ldb, int ldc,
              size_t sA, size_t sB, size_t sC)
{
    const int m0 = blockIdx.y * TM;
    const int n0 = blockIdx.x * TN;
    if (CAUSAL && n0 > m0 + TM - 1) return;

    A += (size_t)blockIdx.z * sA;
    B += (size_t)blockIdx.z * sB;

    const int kend  = KLIM ? (m0 + TM) : K;
    const int niter = kend / BKH;            // >= 4 always

    extern __shared__ __align__(16) char smem[];
    const uint32_t AsB = smem_u32(smem);                    // STAGES x ABUF
    const uint32_t BsB = AsB + STAGES * ABUF;               // STAGES x BBUF

    const int tid    = threadIdx.x;
    const int lane   = tid & 31;
    const int wid    = tid >> 5;
    const int warp_m = (wid & 1) * 64;
    const int warp_n = (wid >> 1) * 64;
    const int gid    = lane >> 2;
    const int tig    = lane & 3;

    // ldmatrix lane addressing (validated in R7-R15)
    const int msel = lane >> 3, mrow = lane & 7;
    const uint32_t off  = (((msel & 1) * 8 + mrow) * SREG + (msel >> 1) * 8) * 2;
    const uint32_t offA = warp_m * SREG * 2 + off;
    const uint32_t offB = warp_n * SREG * 2 + off;

    // cp.async chunk mapping: 16B chunks; row = tid>>2, col16 = tid&3
    const int crow = tid >> 2;               // 0..63
    const int ccol = tid & 3;                // 0..3
    const uint32_t dA0 = (crow * SREG + ccol * 8) * 2;          // bytes in stage
    const uint32_t dA1 = ((crow + 64) * SREG + ccol * 8) * 2;
    const __half* gA0 = A + (size_t)(m0 + crow)      * lda + ccol * 8;
    const __half* gA1 = A + (size_t)(m0 + crow + 64) * lda + ccol * 8;
    const __half* gB[4] = {
        B + (size_t)(n0 + crow)       * ldb + ccol * 8,
        B + (size_t)(n0 + crow + 64)  * ldb + ccol * 8,
        B + (size_t)(n0 + crow + 128) * ldb + ccol * 8,
        B + (size_t)(n0 + crow + 192) * ldb + ccol * 8 };

    float acc[4][8][4];
#pragma unroll
    for (int i = 0; i < 4; i++)
#pragma unroll
        for (int j = 0; j < 8; j++)
#pragma unroll
            for (int r = 0; r < 4; r++) acc[i][j][r] = 0.f;

    // prologue: stages 0..2
#pragma unroll
    for (int s = 0; s < STAGES - 1; ++s) {
        const int ko = s * BKH;
        const uint32_t aD = AsB + s * ABUF, bD = BsB + s * BBUF;
        cp16(aD + dA0, gA0 + ko);
        cp16(aD + dA1, gA1 + ko);
#pragma unroll
        for (int r = 0; r < 4; ++r)
            cp16(bD + dA0 + (r * 64) * SREG * 2, gB[r] + ko);
        CP_COMMIT();
    }

    for (int it = 0; it < niter; ++it) {
        CP_WAIT2();                  // stage it complete (<=2 groups pending)
        __syncthreads();             // data visible CTA-wide; prior readers done

        // issue stage it+3 into buffer (it+3)%4 (freed by the barrier above)
        if (it + 3 < niter) {
            const int s = (it + 3) % STAGES;
            const int ko = (it + 3) * BKH;
            const uint32_t aD = AsB + s * ABUF, bD = BsB + s * BBUF;
            cp16(aD + dA0, gA0 + ko);
            cp16(aD + dA1, gA1 + ko);
#pragma unroll
            for (int r = 0; r < 4; ++r)
                cp16(bD + dA0 + (r * 64) * SREG * 2, gB[r] + ko);
        }
        CP_COMMIT();                 // one commit per iter keeps group accounting

        const uint32_t aBuf = AsB + (it % STAGES) * ABUF;
        const uint32_t bBuf = BsB + (it % STAGES) * BBUF;

        // hoisted fragment loads for both kc halves
        uint32_t af[2][4][4], bf[2][8][2];
#pragma unroll
        for (int kc = 0; kc < 2; ++kc) {
#pragma unroll
            for (int i = 0; i < 4; ++i)
                ldmx4(af[kc][i], aBuf + offA + i * (16 * SREG * 2) + kc * 32);
#pragma unroll
            for (int jp = 0; jp < 4; ++jp) {
                uint32_t r[4];
                ldmx4(r, bBuf + offB + jp * (16 * SREG * 2) + kc * 32);
                bf[kc][2 * jp][0]     = r[0]; bf[kc][2 * jp + 1][0] = r[1];
                bf[kc][2 * jp][1]     = r[2]; bf[kc][2 * jp + 1][1] = r[3];
            }
        }
#pragma unroll
        for (int kc = 0; kc < 2; ++kc)
#pragma unroll
            for (int i = 0; i < 4; ++i)
#pragma unroll
                for (int j = 0; j < 8; ++j)
                    mma_f16(acc[i][j], af[kc][i], bf[kc][j]);
    }

    // epilogue
    if (HOUT) {
        __half* Ch = (__half*)Cv + (size_t)blockIdx.z * sC;
#pragma unroll
        for (int i = 0; i < 4; ++i) {
            const int r0 = m0 + warp_m + i * 16 + gid;
#pragma unroll
            for (int j = 0; j < 8; ++j) {
                const int c0 = n0 + warp_n + j * 8 + 2 * tig;
                *(uint32_t*)(Ch + (size_t)(r0)     * ldc + c0) = f2h2(acc[i][j][0], acc[i][j][1]);
                *(uint32_t*)(Ch + (size_t)(r0 + 8) * ldc + c0) = f2h2(acc[i][j][2], acc[i][j][3]);
            }
        }
    } else {
        float* Cf = (float*)Cv + (size_t)blockIdx.z * sC;
#pragma unroll
        for (int i = 0; i < 4; ++i) {
            const int r0 = m0 + warp_m + i * 16 + gid;
#pragma unroll
            for (int j = 0; j < 8; ++j) {
                const int c0 = n0 + warp_n + j * 8 + 2 * tig;
                *(float2*)(Cf + (size_t)(r0)     * ldc + c0) = make_float2(acc[i][j][0], acc[i][j][1]);
                *(float2*)(Cf + (size_t)(r0 + 8) * ldc + c0) = make_float2(acc[i][j][2], acc[i][j][3]);
            }
        }
    }
}

// ---------------------------------------------------------------------------
__global__ void f2h_kernel(const float4* __restrict__ in, uint2* __restrict__ out, int n4)
{
    int i = blockIdx.x * blockDim.x + threadIdx.x;
    if (i < n4) {
        float4 v = in[i];
        out[i] = make_uint2(f2h2(v.x, v.y), f2h2(v.z, v.w));
    }
}

__global__ void transpose_f2h(const float* __restrict__ in, __half* __restrict__ out,
                              int R, int C)
{
    __shared__ float t[32][33];
    const int c0 = blockIdx.x * 32, r0 = blockIdx.y * 32;
    const int tx = threadIdx.x, ty = threadIdx.y;
#pragma unroll
    for (int i = 0; i < 32; i += 8)
        t[ty + i][tx] = in[(size_t)(r0 + ty + i) * C + c0 + tx];
    __syncthreads();
#pragma unroll
    for (int i = 0; i < 32; i += 8)
        out[(size_t)(c0 + ty + i) * R + r0 + tx] = __float2half_rn(t[tx][ty + i]);
}

__global__ void transpose_h(const __half* __restrict__ in, __half* __restrict__ out,
                            int R, int C, size_t sIn, size_t sOut)
{
    __shared__ __half t[32][34];
    in  += (size_t)blockIdx.z * sIn;
    out += (size_t)blockIdx.z * sOut;
    const int c0 = blockIdx.x * 32, r0 = blockIdx.y * 32;
    const int tx = threadIdx.x, ty = threadIdx.y;
#pragma unroll
    for (int i = 0; i < 32; i += 8)
        t[ty + i][tx] = in[(size_t)(r0 + ty + i) * C + c0 + tx];
    __syncthreads();
#pragma unroll
    for (int i = 0; i < 32; i += 8)
        out[(size_t)(c0 + ty + i) * R + r0 + tx] = t[tx][ty + i];
}

// ---------------------------------------------------------------------------
// Causal softmax, register-cached: each of 256 threads owns exactly 8 row
// elements (2 x float4). Row is read ONCE; probs written as fp16 (uint4).
// ---------------------------------------------------------------------------
__global__ void softmax_causal_kernel(const float* __restrict__ S, __half* __restrict__ P,
                                      int seq, float scale)
{
    const int q = blockIdx.x;
    const size_t roff = ((size_t)blockIdx.y * seq + q) * (size_t)seq;
    const float4* row4 = (const float4*)(S + roff);
    uint4* prow = (uint4*)(P + roff);
    const int L = q + 1;
    const int tid = threadIdx.x;
    const int i0 = tid * 8;
    __shared__ float redm[8], reds[8];

    float f[8];
    {
        float4 v0 = row4[tid * 2];
        float4 v1 = row4[tid * 2 + 1];
        f[0] = v0.x; f[1] = v0.y; f[2] = v0.z; f[3] = v0.w;
        f[4] = v1.x; f[5] = v1.y; f[6] = v1.z; f[7] = v1.w;
    }

    float m = -3.4e38f;
#pragma unroll
    for (int k = 0; k < 8; ++k)
        if (i0 + k < L) m = fmaxf(m, f[k]);
#pragma unroll
    for (int o = 16; o; o >>= 1) m = fmaxf(m, __shfl_xor_sync(0xffffffffu, m, o));
    if ((tid & 31) == 0) redm[tid >> 5] = m;
    __syncthreads();
    m = fmaxf(fmaxf(fmaxf(redm[0], redm[1]), fmaxf(redm[2], redm[3])),
              fmaxf(fmaxf(redm[4], redm[5]), fmaxf(redm[6], redm[7])));

    float s = 0.f;
#pragma unroll
    for (int k = 0; k < 8; ++k) {
        if (i0 + k < L) { f[k] = __expf(scale * (f[k] - m)); s += f[k]; }
        else            { f[k] = 0.f; }
    }
#pragma unroll
    for (int o = 16; o; o >>= 1) s += __shfl_xor_sync(0xffffffffu, s, o);
    if ((tid & 31) == 0) reds[tid >> 5] = s;
    __syncthreads();
    s = (reds[0] + reds[1]) + (reds[2] + reds[3]) +
        (reds[4] + reds[5]) + (reds[6] + reds[7]);
    const float inv = 1.f / s;

    prow[tid] = make_uint4(f2h2(f[0] * inv, f[1] * inv), f2h2(f[2] * inv, f[3] * inv),
                           f2h2(f[4] * inv, f[5] * inv), f2h2(f[6] * inv, f[7] * inv));
}

// ---------------------------------------------------------------------------
extern "C" void kernel_launch(void* const* d_in, const int* in_sizes, int n_in,
                              void* d_out, int out_size)
{
    const float* x  = (const float*)d_in[0];
    const float* Wq = (const float*)d_in[1];
    const float* Wk = (const float*)d_in[2];
    const float* Wv = (const float*)d_in[3];
    float* out = (float*)d_out;

    static __half *xh = nullptr, *wth, *qkvh, *vth, *ph;
    static float  *s;
    if (!xh) {   // first call is outside graph capture
        cudaFuncSetAttribute(mma_gemm<0,0,1>, cudaFuncAttributeMaxDynamicSharedMemorySize, SMEM_TOTAL);
        cudaFuncSetAttribute(mma_gemm<1,0,0>, cudaFuncAttributeMaxDynamicSharedMemorySize, SMEM_TOTAL);
        cudaFuncSetAttribute(mma_gemm<0,1,0>, cudaFuncAttributeMaxDynamicSharedMemorySize, SMEM_TOTAL);
        cudaGetSymbolAddress((void**)&xh,   g_xh);
        cudaGetSymbolAddress((void**)&wth,  g_wth);
        cudaGetSymbolAddress((void**)&qkvh, g_qkvh);
        cudaGetSymbolAddress((void**)&vth,  g_vth);
        cudaGetSymbolAddress((void**)&s,    g_s);
        cudaGetSymbolAddress((void**)&ph,   g_ph);
    }
    __half* qh = qkvh;
    __half* kh = qkvh + (size_t)MTOT * DIM;
    __half* vh = qkvh + 2 * (size_t)MTOT * DIM;

    // 0a) x -> fp16
    {
        int n4 = MTOT * DIM / 4;
        f2h_kernel<<<(n4 + 255) / 256, 256>>>((const float4*)x, (uint2*)xh, n4);
    }
    // 0b) W^T -> fp16 (K-major B operands)
    {
        dim3 g(DIM / 32, DIM / 32), b(32, 8);
        transpose_f2h<<<g, b>>>(Wq, wth,                         DIM, DIM);
        transpose_f2h<<<g, b>>>(Wk, wth + (size_t)DIM * DIM,     DIM, DIM);
        transpose_f2h<<<g, b>>>(Wv, wth + 2 * (size_t)DIM * DIM, DIM, DIM);
    }
    // 1) fused projections -> Q,K,V (fp16)
    {
        dim3 g(DIM / TN, MTOT / TM, 3);
        mma_gemm<0,0,1><<<g, 256, SMEM_TOTAL>>>(xh, wth, qkvh, DIM, DIM, DIM, DIM,
                                                0, (size_t)DIM * DIM, (size_t)MTOT * DIM);
    }
    // 2) V^T per batch (fp16)
    {
        dim3 g(DIM / 32, SEQ / 32, BATCH), b(32, 8);
        transpose_h<<<g, b>>>(vh, vth, SEQ, DIM, (size_t)SEQ * DIM, (size_t)SEQ * DIM);
    }
    // 3) scores: S[b] = Q[b] * K[b]^T (fp32 out); skip fully-masked tiles
    {
        dim3 g(SEQ / TN, SEQ / TM, BATCH);
        mma_gemm<1,0,0><<<g, 256, SMEM_TOTAL>>>(qh, kh, s, DIM, DIM, DIM, SEQ,
                                                (size_t)SEQ * DIM, (size_t)SEQ * DIM,
                                                (size_t)SEQ * SEQ);
    }
    // 4) causal softmax (scale 1/32) -> P fp16, tail zeroed
    {
        dim3 g(SEQ, BATCH);
        softmax_causal_kernel<<<g, 256>>>(s, ph, SEQ, 0.03125f);
    }
    // 5) O[b] = P[b] * V[b] (fp32 out), K limited to m0+TM
    {
        dim3 g(DIM / TN, SEQ / TM, BATCH);
        mma_gemm<0,1,0><<<g, 256, SMEM_TOTAL>>>(ph, vth, out, SEQ, SEQ, SEQ, DIM,
                                                (size_t)SEQ * SEQ, (size_t)SEQ * DIM,
                                                (size_t)SEQ * DIM);
    }
}